// round 2
// baseline (speedup 1.0000x reference)
#include <cuda_runtime.h>
#include <cuda_bf16.h>
#include <cstdint>

#define T_SEQ 512
#define DIN   32
#define HDIM  64
#define G     256     // 4*H gate rows
#define NB    8       // batches per CTA
#define NTHR  256
#define SW0_S 68      // Whh0 row stride (floats): 68/4=17 odd -> conflict-free LDS.128
#define SW1_S 132     // [Wih1|Whh1] row stride: 132/4=33 odd -> conflict-free
#define ZB_S  9       // gate-exchange stride: 9 coprime 32 -> conflict-free scalar

// smem floats:
//   sW0: 256*68 =17408 | sW1: 256*132=33792 | zb: 256*9=2304
//   in0: 8*96 = 768 (x|h0) | in1: 8*128 = 1024 (h0|h1)
#define SMEM_FLOATS (G*SW0_S + G*SW1_S + G*ZB_S + NB*96 + NB*128)

__device__ __forceinline__ unsigned long long pack2(float lo, float hi) {
    unsigned long long r;
    asm("mov.b64 %0, {%1,%2};" : "=l"(r) : "f"(lo), "f"(hi));
    return r;
}
__device__ __forceinline__ void fma2(unsigned long long& d,
                                     unsigned long long a, unsigned long long b) {
    asm("fma.rn.f32x2 %0, %1, %2, %0;" : "+l"(d) : "l"(a), "l"(b));
}
__device__ __forceinline__ float hsum2(unsigned long long v) {
    float lo, hi;
    asm("mov.b64 {%0,%1}, %2;" : "=f"(lo), "=f"(hi) : "l"(v));
    return lo + hi;
}
__device__ __forceinline__ float sigmoid_fast(float x) {
    return __fdividef(1.0f, 1.0f + __expf(-x));
}
__device__ __forceinline__ float tanh_fast(float x) {
    // 1 - 2/(exp(2x)+1): correct saturation both directions
    return 1.0f - __fdividef(2.0f, __expf(2.0f * x) + 1.0f);
}

extern __shared__ float smem[];

__global__ void __launch_bounds__(NTHR, 1)
lstm_return_kernel(const float* __restrict__ x,
                   const float* __restrict__ Wih0, const float* __restrict__ Whh0,
                   const float* __restrict__ bih0, const float* __restrict__ bhh0,
                   const float* __restrict__ Wih1, const float* __restrict__ Whh1,
                   const float* __restrict__ bih1, const float* __restrict__ bhh1,
                   const float* __restrict__ W1,   const float* __restrict__ b1,
                   const float* __restrict__ W2,   const float* __restrict__ b2,
                   float* __restrict__ out)
{
    float* sW0 = smem;                 // [256][68]  Whh0
    float* sW1 = sW0 + G * SW0_S;      // [256][132] [Wih1|Whh1]
    float* zb  = sW1 + G * SW1_S;      // [256][9]   activated gates
    float* in0 = zb  + G * ZB_S;       // [8][96]    x(0:32) | h0(32:96)
    float* in1 = in0 + NB * 96;        // [8][128]   h0(0:64) | h1(64:128)

    const int tid   = threadIdx.x;
    const int j     = tid;                       // gate row
    const int bbase = blockIdx.x * NB;

    // ---- stage weights into smem ----
    for (int i = tid; i < G * HDIM; i += NTHR) {
        int r = i >> 6, c = i & 63;
        sW0[r * SW0_S + c]        = Whh0[i];
        sW1[r * SW1_S + c]        = Wih1[i];
        sW1[r * SW1_S + HDIM + c] = Whh1[i];
    }
    for (int i = tid; i < NB * 96;  i += NTHR) in0[i] = 0.0f;
    for (int i = tid; i < NB * 128; i += NTHR) in1[i] = 0.0f;

    // ---- x-path weights (row j of Wih0) in registers, packed f32x2 ----
    unsigned long long wxp[16];
#pragma unroll
    for (int k = 0; k < 16; k++)
        wxp[k] = pack2(Wih0[j * DIN + 2 * k], Wih0[j * DIN + 2 * k + 1]);

    const float bsum0 = bih0[j] + bhh0[j];
    const float bsum1 = bih1[j] + bhh1[j];
    const bool  row_is_tanh = ((j >> 6) == 2);   // g-gate rows

    // cell-state owner mapping: u = tid&63, batches (tid>>6) and (tid>>6)+4
    const int cu = tid & 63;
    const int cb = tid >> 6;          // 0..3
    float c0a = 0.f, c0b = 0.f, c1a = 0.f, c1b = 0.f;

    // x prefetch: thread -> (batch xb, channel xk), coalesced 128B rows
    const int xb = tid >> 5, xk = tid & 31;
    const float* xptr = x + ((size_t)(bbase + xb) * T_SEQ) * DIN + xk;
    float xreg = xptr[0];

    const float* w0row = sW0 + j * SW0_S;
    const float* w1row = sW1 + j * SW1_S;

    __syncthreads();

    for (int t = 0; t < T_SEQ; t++) {
        // stage x(t); prefetch x(t+1)
        in0[xb * 96 + xk] = xreg;
        if (t + 1 < T_SEQ) xreg = xptr[(t + 1) * DIN];
        __syncthreads();                                  // (A)

        // ===== layer 0 gates: z0 = x@Wih0^T + h0@Whh0^T + bias =====
        {
            unsigned long long acc[NB];
#pragma unroll
            for (int b = 0; b < NB; b++) acc[b] = pack2(bsum0, 0.0f);

            // x part: weights in regs, inputs broadcast LDS.128
#pragma unroll
            for (int kc = 0; kc < 8; kc++) {
                const unsigned long long w0 = wxp[2 * kc], w1 = wxp[2 * kc + 1];
#pragma unroll
                for (int b = 0; b < NB; b++) {
                    ulonglong2 iv = *(const ulonglong2*)(in0 + b * 96 + 4 * kc);
                    fma2(acc[b], w0, iv.x);
                    fma2(acc[b], w1, iv.y);
                }
            }
            // h part: weights LDS.128 (conflict-free pad-68), inputs broadcast
#pragma unroll
            for (int kc = 0; kc < 16; kc++) {
                ulonglong2 wv = *(const ulonglong2*)(w0row + 4 * kc);
#pragma unroll
                for (int b = 0; b < NB; b++) {
                    ulonglong2 iv = *(const ulonglong2*)(in0 + b * 96 + 32 + 4 * kc);
                    fma2(acc[b], wv.x, iv.x);
                    fma2(acc[b], wv.y, iv.y);
                }
            }
#pragma unroll
            for (int b = 0; b < NB; b++) {
                float z = hsum2(acc[b]);
                zb[j * ZB_S + b] = row_is_tanh ? tanh_fast(z) : sigmoid_fast(z);
            }
        }
        __syncthreads();                                  // (B)

        // ===== layer 0 cell update (owner: (cu, cb) and (cu, cb+4)) =====
        {
            const float* zc = zb + cu * ZB_S;
            {
                float i_ = zc[0 * 64 * ZB_S + cb];
                float f_ = zc[1 * 64 * ZB_S + cb];
                float g_ = zc[2 * 64 * ZB_S + cb];
                float o_ = zc[3 * 64 * ZB_S + cb];
                c0a = f_ * c0a + i_ * g_;
                float h = o_ * tanh_fast(c0a);
                in0[cb * 96 + 32 + cu] = h;
                in1[cb * 128 + cu]     = h;
            }
            {
                int b2i = cb + 4;
                float i_ = zc[0 * 64 * ZB_S + b2i];
                float f_ = zc[1 * 64 * ZB_S + b2i];
                float g_ = zc[2 * 64 * ZB_S + b2i];
                float o_ = zc[3 * 64 * ZB_S + b2i];
                c0b = f_ * c0b + i_ * g_;
                float h = o_ * tanh_fast(c0b);
                in0[b2i * 96 + 32 + cu] = h;
                in1[b2i * 128 + cu]     = h;
            }
        }
        __syncthreads();                                  // (C)

        // ===== layer 1 gates: z1 = [h0|h1] @ [Wih1|Whh1]^T + bias =====
        {
            unsigned long long acc[NB];
#pragma unroll
            for (int b = 0; b < NB; b++) acc[b] = pack2(bsum1, 0.0f);
#pragma unroll
            for (int kc = 0; kc < 32; kc++) {
                ulonglong2 wv = *(const ulonglong2*)(w1row + 4 * kc);
#pragma unroll
                for (int b = 0; b < NB; b++) {
                    ulonglong2 iv = *(const ulonglong2*)(in1 + b * 128 + 4 * kc);
                    fma2(acc[b], wv.x, iv.x);
                    fma2(acc[b], wv.y, iv.y);
                }
            }
#pragma unroll
            for (int b = 0; b < NB; b++) {
                float z = hsum2(acc[b]);
                zb[j * ZB_S + b] = row_is_tanh ? tanh_fast(z) : sigmoid_fast(z);
            }
        }
        __syncthreads();                                  // (D)

        // ===== layer 1 cell update =====
        {
            const float* zc = zb + cu * ZB_S;
            {
                float i_ = zc[0 * 64 * ZB_S + cb];
                float f_ = zc[1 * 64 * ZB_S + cb];
                float g_ = zc[2 * 64 * ZB_S + cb];
                float o_ = zc[3 * 64 * ZB_S + cb];
                c1a = f_ * c1a + i_ * g_;
                in1[cb * 128 + 64 + cu] = o_ * tanh_fast(c1a);
            }
            {
                int b2i = cb + 4;
                float i_ = zc[0 * 64 * ZB_S + b2i];
                float f_ = zc[1 * 64 * ZB_S + b2i];
                float g_ = zc[2 * 64 * ZB_S + b2i];
                float o_ = zc[3 * 64 * ZB_S + b2i];
                c1b = f_ * c1b + i_ * g_;
                in1[b2i * 128 + 64 + cu] = o_ * tanh_fast(c1b);
            }
        }
        // no sync needed here: (A) next iteration orders zb/in1 reuse
    }

    __syncthreads();   // final h1 visible to head

    // ===== head: out = relu(h1 @ W1^T + b1) @ W2^T + b2 =====
    {
        const int hb = tid >> 5;    // batch 0..7
        const int hu = tid & 31;    // hidden unit 0..31
        const float* w1r = W1 + hu * HDIM;
        const float* hv  = in1 + hb * 128 + 64;
        float acc = b1[hu];
#pragma unroll
        for (int k = 0; k < HDIM; k++) acc += w1r[k] * hv[k];
        acc = fmaxf(acc, 0.0f) * W2[hu];
        zb[hb * 32 + hu] = acc;     // reuse zb as scratch
    }
    __syncthreads();
    if (tid < NB) {
        float s = b2[0];
#pragma unroll
        for (int u = 0; u < 32; u++) s += zb[tid * 32 + u];
        out[bbase + tid] = s;
    }
}

extern "C" void kernel_launch(void* const* d_in, const int* in_sizes, int n_in,
                              void* d_out, int out_size) {
    (void)in_sizes; (void)n_in; (void)out_size;
    const float* x    = (const float*)d_in[0];
    const float* Wih0 = (const float*)d_in[1];
    const float* Whh0 = (const float*)d_in[2];
    const float* bih0 = (const float*)d_in[3];
    const float* bhh0 = (const float*)d_in[4];
    const float* Wih1 = (const float*)d_in[5];
    const float* Whh1 = (const float*)d_in[6];
    const float* bih1 = (const float*)d_in[7];
    const float* bhh1 = (const float*)d_in[8];
    const float* W1   = (const float*)d_in[9];
    const float* b1   = (const float*)d_in[10];
    const float* W2   = (const float*)d_in[11];
    const float* b2   = (const float*)d_in[12];
    float* out = (float*)d_out;

    const size_t smem_bytes = (size_t)SMEM_FLOATS * sizeof(float);
    cudaFuncSetAttribute(lstm_return_kernel,
                         cudaFuncAttributeMaxDynamicSharedMemorySize,
                         (int)smem_bytes);
    lstm_return_kernel<<<1024 / NB, NTHR, smem_bytes>>>(
        x, Wih0, Whh0, bih0, bhh0, Wih1, Whh1, bih1, bhh1,
        W1, b1, W2, b2, out);
}